// round 5
// baseline (speedup 1.0000x reference)
#include <cuda_runtime.h>

// GraphConvolution: out[dst] = sum_e w_e * (x W + b)[src_e]
// Restructured: agg[dst] = sum_e w_e * x[src_e];  degw[dst] = sum_e w_e
//               out = agg @ W + degw[:,None] * b[None,:]
//
// Inputs (metadata order): x[N,128] f32, W[128,128] f32, b[128] f32,
//                          edge_weight[E] f32, edge_src[E] i32, edge_dst[E] i32 (sorted)
// Output: out[N,128] f32

#define MAX_NODES 100000
#define D 128
#define D4 32   // D / 4

// Scratch (allocation-free rule: __device__ globals)
__device__ float g_agg[(size_t)MAX_NODES * D];   // 51.2 MB
__device__ float g_degw[MAX_NODES];

// ---------------------------------------------------------------------------
// Kernel 1: zero the scratch
// ---------------------------------------------------------------------------
__global__ void gc_zero_kernel(int n_nodes) {
    const int total4 = n_nodes * D4;
    float4 z = make_float4(0.f, 0.f, 0.f, 0.f);
    float4* a4 = reinterpret_cast<float4*>(g_agg);
    for (int i = blockIdx.x * blockDim.x + threadIdx.x; i < total4;
         i += gridDim.x * blockDim.x)
        a4[i] = z;
    for (int i = blockIdx.x * blockDim.x + threadIdx.x; i < n_nodes;
         i += gridDim.x * blockDim.x)
        g_degw[i] = 0.f;
}

// ---------------------------------------------------------------------------
// Kernel 2: edge aggregation.
// edge_dst is SORTED: each warp owns a contiguous edge range, keeps a float4
// accumulator (128 floats across 32 lanes) for the current destination, and
// flushes with atomicAdd only on segment change / range end.
// Edge metadata is read coalesced (one edge per lane) then shfl-broadcast.
// ---------------------------------------------------------------------------
__global__ void gc_aggregate_kernel(const float4* __restrict__ x4,
                                    const float* __restrict__ ew,
                                    const int* __restrict__ esrc,
                                    const int* __restrict__ edst,
                                    int E, int epw) {
    const int gwarp = (blockIdx.x * blockDim.x + threadIdx.x) >> 5;
    const int lane  = threadIdx.x & 31;
    long start = (long)gwarp * epw;
    if (start >= E) return;
    long end = start + epw;
    if (end > E) end = E;

    float4 acc = make_float4(0.f, 0.f, 0.f, 0.f);
    float  wsum = 0.f;
    int    cur  = -1;

    for (long base = start; base < end; base += 32) {
        long e = base + lane;
        int  s = 0, d = -1;
        float w = 0.f;
        if (e < end) { s = esrc[e]; d = edst[e]; w = ew[e]; }
        const int cnt = (int)min((long)32, end - base);

        for (int i = 0; i < cnt; i++) {
            const int   src = __shfl_sync(0xffffffffu, s, i);
            const int   dst = __shfl_sync(0xffffffffu, d, i);
            const float wt  = __shfl_sync(0xffffffffu, w, i);

            if (dst != cur) {
                if (cur >= 0) {
                    float* p = g_agg + (size_t)cur * D + lane * 4;
                    atomicAdd(p + 0, acc.x);
                    atomicAdd(p + 1, acc.y);
                    atomicAdd(p + 2, acc.z);
                    atomicAdd(p + 3, acc.w);
                    if (lane == 0) atomicAdd(g_degw + cur, wsum);
                }
                acc  = make_float4(0.f, 0.f, 0.f, 0.f);
                wsum = 0.f;
                cur  = dst;
            }
            const float4 v = x4[(size_t)src * D4 + lane];
            acc.x += wt * v.x;
            acc.y += wt * v.y;
            acc.z += wt * v.z;
            acc.w += wt * v.w;
            wsum  += wt;
        }
    }
    if (cur >= 0) {
        float* p = g_agg + (size_t)cur * D + lane * 4;
        atomicAdd(p + 0, acc.x);
        atomicAdd(p + 1, acc.y);
        atomicAdd(p + 2, acc.z);
        atomicAdd(p + 3, acc.w);
        if (lane == 0) atomicAdd(g_degw + cur, wsum);
    }
}

// ---------------------------------------------------------------------------
// Kernel 3: out = agg @ W + degw * b   (M=n_nodes, K=128, N=128)
// Block tile: 64 rows x 128 cols, 256 threads, per-thread 8x4 register tile.
// K processed in two 64-halves so (A-tile + W-tile) = exactly 48 KB smem.
// ---------------------------------------------------------------------------
__global__ void __launch_bounds__(256)
gc_gemm_kernel(const float* __restrict__ W,
               const float* __restrict__ b,
               float* __restrict__ out,
               int n_nodes) {
    __shared__ float As[64 * 64];    // [m][k-half]  16 KB
    __shared__ float Ws[64 * 128];   // [k-half][j]  32 KB

    const int tid = threadIdx.x;
    const int m0  = blockIdx.x * 64;
    const int c   = tid & 31;        // column group: cols 4c..4c+3
    const int r   = tid >> 5;        // warp id: rows r*8 .. r*8+7

    float acc[8][4];
#pragma unroll
    for (int i = 0; i < 8; i++)
#pragma unroll
        for (int t = 0; t < 4; t++) acc[i][t] = 0.f;

    const float4* agg4 = reinterpret_cast<const float4*>(g_agg);
    const float4* W4   = reinterpret_cast<const float4*>(W);
    float4* As4 = reinterpret_cast<float4*>(As);
    float4* Ws4 = reinterpret_cast<float4*>(Ws);

    for (int kp = 0; kp < 2; kp++) {
        if (kp) __syncthreads();   // compute of previous phase done

        // Load A tile: 64 rows x 16 float4 (k-half) = 1024 float4
        for (int i = tid; i < 64 * 16; i += 256) {
            const int m  = i >> 4;
            const int k4 = i & 15;
            const int gm = m0 + m;
            float4 v = make_float4(0.f, 0.f, 0.f, 0.f);
            if (gm < n_nodes) v = agg4[(size_t)gm * D4 + kp * 16 + k4];
            As4[i] = v;
        }
        // Load W tile: 64 k-rows x 32 float4 = 2048 float4
        for (int i = tid; i < 64 * 32; i += 256) {
            const int k  = i >> 5;
            const int j4 = i & 31;
            Ws4[i] = W4[(size_t)(kp * 64 + k) * D4 + j4];
        }
        __syncthreads();

        // Compute
#pragma unroll
        for (int k4 = 0; k4 < 16; k4++) {
            const float4 w0 = Ws4[(k4 * 4 + 0) * 32 + c];
            const float4 w1 = Ws4[(k4 * 4 + 1) * 32 + c];
            const float4 w2 = Ws4[(k4 * 4 + 2) * 32 + c];
            const float4 w3 = Ws4[(k4 * 4 + 3) * 32 + c];
#pragma unroll
            for (int i = 0; i < 8; i++) {
                const float4 av = As4[(r * 8 + i) * 16 + k4];
                acc[i][0] += av.x * w0.x + av.y * w1.x + av.z * w2.x + av.w * w3.x;
                acc[i][1] += av.x * w0.y + av.y * w1.y + av.z * w2.y + av.w * w3.y;
                acc[i][2] += av.x * w0.z + av.y * w1.z + av.z * w2.z + av.w * w3.z;
                acc[i][3] += av.x * w0.w + av.y * w1.w + av.z * w2.w + av.w * w3.w;
            }
        }
    }

    // Epilogue: + degw[m] * b[j]
    const float4 bv = reinterpret_cast<const float4*>(b)[c];
    float4* out4 = reinterpret_cast<float4*>(out);
#pragma unroll
    for (int i = 0; i < 8; i++) {
        const int gm = m0 + r * 8 + i;
        if (gm < n_nodes) {
            const float dw = g_degw[gm];
            float4 o;
            o.x = acc[i][0] + dw * bv.x;
            o.y = acc[i][1] + dw * bv.y;
            o.z = acc[i][2] + dw * bv.z;
            o.w = acc[i][3] + dw * bv.w;
            out4[(size_t)gm * D4 + c] = o;
        }
    }
}

// ---------------------------------------------------------------------------
extern "C" void kernel_launch(void* const* d_in, const int* in_sizes, int n_in,
                              void* d_out, int out_size) {
    const float* x    = (const float*)d_in[0];
    const float* W    = (const float*)d_in[1];
    const float* b    = (const float*)d_in[2];
    const float* ew   = (const float*)d_in[3];
    const int*   esrc = (const int*)d_in[4];
    const int*   edst = (const int*)d_in[5];
    float*       out  = (float*)d_out;

    const int n_nodes = in_sizes[0] / D;
    const int E       = in_sizes[4];

    // 1) zero scratch
    gc_zero_kernel<<<1184, 256>>>(n_nodes);

    // 2) edge aggregation: 128 edges per warp
    const int EPW    = 128;
    const int nwarps = (E + EPW - 1) / EPW;
    const int ablk   = (nwarps * 32 + 255) / 256;
    gc_aggregate_kernel<<<ablk, 256>>>(
        reinterpret_cast<const float4*>(x), ew, esrc, edst, E, EPW);

    // 3) dense projection + bias
    gc_gemm_kernel<<<(n_nodes + 63) / 64, 256>>>(W, b, out, n_nodes);
}